// round 10
// baseline (speedup 1.0000x reference)
#include <cuda_runtime.h>

#define Bb 16
#define Tt 160
#define Uu 80
#define U1 81
#define Vv 512
#define NDIAG 240     // diagonals d = t+u in [0,239]
#define DSTR 88       // diagonal row stride (floats), 16B aligned
#define RPB (Tt*U1)   // rows per batch = 12960
#define L2E 1.4426950408889634f
#define LN2 0.6931471805599453f
#define NEG_INF __int_as_float(0xFF800000)

// Scratch (allocation-free rule). Tables: log2-domain, anti-diagonal layout.
__device__ float g_blank[Bb*NDIAG*DSTR];
__device__ float g_lab  [Bb*NDIAG*DSTR];
__device__ float g_ll   [Bb];
__device__ int   g_done;              // dp completion counter; self-resetting
__device__ int   g_cnt  [Bb*Tt];      // rows published per (b,t); self-resetting
__device__ int   g_padc [Bb];         // pad-fill done per batch; self-resetting
__device__ int   g_perm [Bb];         // production slot -> batch (dtar desc)
__device__ int   g_perm_ready;        // sticky: inputs fixed => perm fixed

// ---------------------------------------------------------------------------
__device__ __forceinline__ float exp_fast(float x) {   // FMA-only
    const float MAGIC = 12582912.0f;                    // 1.5 * 2^23
    float z = fmaf(x, L2E, MAGIC);
    float w = z - MAGIC;
    float f = fmaf(x, L2E, -w);
    float p =               9.6181291076e-3f;
    p = fmaf(p, f, 5.5504108664e-2f);
    p = fmaf(p, f, 2.4022650696e-1f);
    p = fmaf(p, f, 6.9314718056e-1f);
    p = fmaf(p, f, 1.0f);
    return __int_as_float(__float_as_int(p) + (__float_as_int(z) << 23));
}

// log2-domain logaddexp of (vs+bl, vl+la). NaN from (-inf)-(-inf) clamped.
__device__ __forceinline__ float dstep(float vs, float vl, float bl, float la) {
    float x = vs + bl;
    float y = vl + la;
    float mx = fmaxf(x, y);
    float mn = fminf(x, y);
    float nd = fmaxf(mn - mx, -126.0f);
    float e;  asm("ex2.approx.f32 %0, %1;" : "=f"(e) : "f"(nd));
    float l;  asm("lg2.approx.f32 %0, %1;" : "=f"(l) : "f"(1.0f + e));
    return mx + l;
}

__device__ __forceinline__ int ld_acq(const int* p) {
    int v;
    asm volatile("ld.acquire.gpu.global.u32 %0, [%1];" : "=r"(v) : "l"(p));
    return v;
}
__device__ __forceinline__ void inc_release(int* p) {
    asm volatile("red.release.gpu.global.add.u32 [%0], 1;" :: "l"(p) : "memory");
}

// ---------------------------------------------------------------------------
// One kernel, three roles by blockIdx.x:
//   [0, Bb)        dp consumer, one batch per block (warp 0 active)
//   [Bb, 2*Bb)     geometry pad fill for one batch (publishes g_padc)
//   [2*Bb, ...)    lse producer: slot = dtar-desc batch permutation,
//                  identity row order within batch (streaming locality)
// ---------------------------------------------------------------------------
__global__ void __launch_bounds__(256, 8)
fused_kernel(const float* __restrict__ logits,
             const int* __restrict__ targets,
             const int* __restrict__ tl_arr,
             const int* __restrict__ ul_arr,
             float* __restrict__ out) {

    if (blockIdx.x >= 2 * Bb) {
        // ===================== LSE producer =====================
        int gw   = ((blockIdx.x - 2 * Bb) * 256 + threadIdx.x) >> 5;
        int lane = threadIdx.x & 31;

        int s = gw / RPB;                 // production slot (completes in order)
        int r = gw - s * RPB;
        int t = r / U1;
        int u = r - t * U1;

        int B;
        if (lane == 0) {                  // slot -> batch (perm by dp block 0)
            while (ld_acq(&g_perm_ready) == 0) __nanosleep(100);
            B = __ldcg(&g_perm[s]);       // post-release value via L2
        }
        B = __shfl_sync(0xffffffffu, B, 0);

        int row = (B * Tt + t) * U1 + u;  // contiguous within the slot
        int o   = (B * NDIAG + (t + u)) * DSTR + u;
        int* cslot = &g_cnt[B * Tt + t];

        if (t >= __ldg(tl_arr + B) || u > __ldg(ul_arr + B)) {  // dead row
            if (lane == 0) {
                g_blank[o] = NEG_INF; g_lab[o] = NEG_INF;
                inc_release(cslot);
            }
            return;
        }

        const float4* p = reinterpret_cast<const float4*>(logits) + (size_t)row * (Vv / 4);
        float4 a  = __ldcs(p + lane);
        float4 b4 = __ldcs(p + lane + 32);
        float4 c  = __ldcs(p + lane + 64);
        float4 dd = __ldcs(p + lane + 96);

        float s0 = (exp_fast(a.x)  + exp_fast(a.y))  + (exp_fast(a.z)  + exp_fast(a.w));
        float s1 = (exp_fast(b4.x) + exp_fast(b4.y)) + (exp_fast(b4.z) + exp_fast(b4.w));
        float s2 = (exp_fast(c.x)  + exp_fast(c.y))  + (exp_fast(c.z)  + exp_fast(c.w));
        float s3 = (exp_fast(dd.x) + exp_fast(dd.y)) + (exp_fast(dd.z) + exp_fast(dd.w));
        float sm = (s0 + s1) + (s2 + s3);
#pragma unroll
        for (int o2 = 16; o2; o2 >>= 1) sm += __shfl_xor_sync(0xffffffffu, sm, o2);

        float blank_logit = __shfl_sync(0xffffffffu, dd.w, 31);  // element 511

        if (lane == 0) {
            float lse2;
            asm("lg2.approx.f32 %0, %1;" : "=f"(lse2) : "f"(sm));
            int tgt = targets[B * Uu + min(u, Uu - 1)];
            float lab_logit = __ldg(logits + (size_t)row * Vv + tgt);
            g_blank[o] = fmaf(blank_logit, L2E, -lse2);
            g_lab[o]   = fmaf(lab_logit,   L2E, -lse2);
            inc_release(cslot);                 // release: after both stores
        }
        return;
    }

    if (blockIdx.x >= Bb) {
        // ===================== PAD fill =====================
        int b = blockIdx.x - Bb;
        float* bbl = g_blank + b * NDIAG * DSTR;
        float* bla = g_lab   + b * NDIAG * DSTR;
        for (int idx = threadIdx.x; idx < NDIAG * DSTR; idx += 256) {
            int d = idx / DSTR;
            int u = idx - d * DSTR;
            int lo = max(0, d - 159), hi = min(d, 80);
            if (u < lo || u > hi) { bbl[idx] = NEG_INF; bla[idx] = NEG_INF; }
        }
        __syncthreads();
        if (threadIdx.x == 0) inc_release(&g_padc[b]);
        return;
    }

    // ===================== DP consumer (blocks 0..15) =====================
    int b = blockIdx.x;

    // Block 0, thread 0: publish production permutation (dtar descending).
    if (b == 0 && threadIdx.x == 0) {
        if (ld_acq(&g_perm_ready) == 0) {
            int dt[Bb];
#pragma unroll
            for (int j = 0; j < Bb; ++j)
                dt[j] = __ldg(tl_arr + j) - 1 + __ldg(ul_arr + j);
#pragma unroll
            for (int j = 0; j < Bb; ++j) {
                int rank = 0;
#pragma unroll
                for (int k = 0; k < Bb; ++k)
                    rank += (dt[k] > dt[j]) || (dt[k] == dt[j] && k < j);
                g_perm[rank] = j;
            }
            asm volatile("st.release.gpu.global.u32 [%0], %1;"
                         :: "l"(&g_perm_ready), "r"(1) : "memory");
        }
    }
    if (threadIdx.x >= 32) return;
    int lane = threadIdx.x;

    // Wait for this batch's pads (written by pad block b).
    if (lane == 0) { while (ld_acq(&g_padc[b]) == 0) __nanosleep(200); }
    __syncwarp();

    int tl = __ldg(tl_arr + b), ul = __ldg(ul_arr + b);
    int dtar = tl - 1 + ul;
    int u0   = lane * 4;
    int uoff = min(u0, 84);
    bool is_owner = (lane == (ul >> 2));
    int  sel = ul & 3;
    float saved = (dtar == 0 && lane == 0) ? 0.0f : NEG_INF;

    const float* bbl = g_blank + b * NDIAG * DSTR;
    const float* bla = g_lab   + b * NDIAG * DSTR;
    int* cnt = g_cnt + b * Tt;

    float v0 = NEG_INF, v1 = NEG_INF, v2 = NEG_INF, v3 = NEG_INF;
    if (lane == 0) v0 = 0.0f;                 // alpha[0][0] (log2 domain)

    for (int c = 0; c < 15; ++c) {
        // Wait for t-slices [16c, 16c+15] (clamped): 81 rows each published.
        int s_t = min(16 * c + lane, Tt - 1);
        for (;;) {
            int have = (lane < 16) ? ld_acq(&cnt[s_t]) : 0x7fffffff;
            if (__all_sync(0xffffffffu, have >= U1)) break;
            __nanosleep(200);
        }

        if (16 * c < dtar) {                   // compute chunk (else wait-only)
            int sd0 = 16 * c;
            float4 cbl = __ldcg(reinterpret_cast<const float4*>(bbl + sd0 * DSTR + uoff));
            float4 cla = __ldcg(reinterpret_cast<const float4*>(bla + sd0 * DSTR + uoff));
#pragma unroll
            for (int k = 0; k < 16; ++k) {
                int d = sd0 + k + 1;
                int dpre = min(d, NDIAG - 1);  // clamped depth-1 prefetch
                float4 nbl = __ldcg(reinterpret_cast<const float4*>(bbl + dpre * DSTR + uoff));
                float4 nla = __ldcg(reinterpret_cast<const float4*>(bla + dpre * DSTR + uoff));

                float vleft = __shfl_up_sync(0xffffffffu, v3,    1);
                float lleft = __shfl_up_sync(0xffffffffu, cla.w, 1);
                if (lane == 0) vleft = NEG_INF;

                float nv0 = dstep(v0, vleft, cbl.x, lleft);
                float nv1 = dstep(v1, v0,    cbl.y, cla.x);
                float nv2 = dstep(v2, v1,    cbl.z, cla.y);
                float nv3 = dstep(v3, v2,    cbl.w, cla.z);

                if (d == dtar && is_owner)
                    saved = sel == 0 ? nv0 : sel == 1 ? nv1 : sel == 2 ? nv2 : nv3;

                v0 = nv0; v1 = nv1; v2 = nv2; v3 = nv3;
                cbl = nbl; cla = nla;
            }
        }
    }

    // All slice waits passed -> all increments observed; reset for replay.
    for (int i = lane; i < Tt; i += 32) cnt[i] = 0;
    if (lane == 0) g_padc[b] = 0;

    if (is_owner) {
        float blank2 = __ldcg(bbl + dtar * DSTR + ul);
        g_ll[b] = saved + blank2;              // log2-domain log-likelihood
        __threadfence();
        int prev = atomicAdd(&g_done, 1);
        if (prev == Bb - 1) {                  // deterministic final reduce
            __threadfence();
            float sll = 0.0f;
#pragma unroll
            for (int i = 0; i < Bb; ++i) sll += __ldcg(&g_ll[i]);
            out[0] = sll * (-LN2 / (float)Bb);
            g_done = 0;                        // reset for next graph replay
        }
    }
}

extern "C" void kernel_launch(void* const* d_in, const int* in_sizes, int n_in,
                              void* d_out, int out_size) {
    const float* logits  = (const float*)d_in[0];
    const int*   targets = (const int*)d_in[1];
    const int*   tl      = (const int*)d_in[2];
    const int*   ul      = (const int*)d_in[3];

    const int ROWS = Bb * Tt * U1;                 // 207360 rows, 8 warps/block
    fused_kernel<<<2 * Bb + ROWS / 8, 256>>>(logits, targets, tl, ul, (float*)d_out);
}

// round 11
// speedup vs baseline: 2.3725x; 2.3725x over previous
#include <cuda_runtime.h>

#define Bb 16
#define Tt 160
#define Uu 80
#define U1 81
#define Vv 512
#define NDIAG 240     // diagonals d = t+u in [0,239]
#define DSTR 88       // diagonal row stride (floats), 16B aligned
#define L2E 1.4426950408889634f
#define LN2 0.6931471805599453f
#define NEG_INF __int_as_float(0xFF800000)
#define PADB Bb       // pad-fill blocks prepended to lse grid

// Scratch (allocation-free rule). Tables: log2-domain, anti-diagonal layout.
__device__ float g_blank[Bb*NDIAG*DSTR];
__device__ float g_lab  [Bb*NDIAG*DSTR];
__device__ float g_ll   [Bb];
__device__ int   g_done;              // dp completion counter; self-resetting

// ---------------------------------------------------------------------------
__device__ __forceinline__ float exp_fast(float x) {   // FMA-only
    const float MAGIC = 12582912.0f;                    // 1.5 * 2^23
    float z = fmaf(x, L2E, MAGIC);
    float w = z - MAGIC;
    float f = fmaf(x, L2E, -w);
    float p =               9.6181291076e-3f;
    p = fmaf(p, f, 5.5504108664e-2f);
    p = fmaf(p, f, 2.4022650696e-1f);
    p = fmaf(p, f, 6.9314718056e-1f);
    p = fmaf(p, f, 1.0f);
    return __int_as_float(__float_as_int(p) + (__float_as_int(z) << 23));
}

// log2-domain logaddexp of (vs+bl, vl+la). NaN from (-inf)-(-inf) clamped.
__device__ __forceinline__ float dstep(float vs, float vl, float bl, float la) {
    float x = vs + bl;
    float y = vl + la;
    float mx = fmaxf(x, y);
    float nd = fmaxf(-fabsf(x - y), -126.0f);
    float e;  asm("ex2.approx.f32 %0, %1;" : "=f"(e) : "f"(nd));
    float l;  asm("lg2.approx.f32 %0, %1;" : "=f"(l) : "f"(1.0f + e));
    return mx + l;
}

__device__ __forceinline__ void cp16(unsigned int s, const void* g) {
    asm volatile("cp.async.cg.shared.global [%0], [%1], 16;" :: "r"(s), "l"(g));
}

// ---------------------------------------------------------------------------
// Kernel 1: blocks [0,PADB): geometry pad fill. Blocks >= PADB: per-row
// logsumexp over V=512 (dead rows write -inf and skip all logit traffic).
// ---------------------------------------------------------------------------
__global__ void __launch_bounds__(256) lse_kernel(const float* __restrict__ logits,
                                                  const int* __restrict__ targets,
                                                  const int* __restrict__ tl_arr,
                                                  const int* __restrict__ ul_arr) {
    if (blockIdx.x < PADB) {
        int b = blockIdx.x;
        float* bbl = g_blank + b * NDIAG * DSTR;
        float* bla = g_lab   + b * NDIAG * DSTR;
        for (int idx = threadIdx.x; idx < NDIAG * DSTR; idx += 256) {
            int d = idx / DSTR;               // const divide -> mul/shift
            int u = idx - d * DSTR;
            int lo = max(0, d - 159), hi = min(d, 80);
            if (u < lo || u > hi) { bbl[idx] = NEG_INF; bla[idx] = NEG_INF; }
        }
        return;
    }

    int gw   = ((blockIdx.x - PADB) * 256 + threadIdx.x) >> 5;  // row id
    int lane = threadIdx.x & 31;

    int u  = gw % U1;
    int bt = gw / U1;
    int t  = bt % Tt;
    int b  = bt / Tt;
    int o  = (b * NDIAG + (t + u)) * DSTR + u;
    if (t >= __ldg(tl_arr + b) || u > __ldg(ul_arr + b)) {  // dead row: -inf cell
        if (lane == 0) { g_blank[o] = NEG_INF; g_lab[o] = NEG_INF; }
        return;
    }

    const float4* p = reinterpret_cast<const float4*>(logits) + (size_t)gw * (Vv / 4);
    float4 a  = __ldcs(p + lane);
    float4 b4 = __ldcs(p + lane + 32);
    float4 c  = __ldcs(p + lane + 64);
    float4 dd = __ldcs(p + lane + 96);

    float s0 = (exp_fast(a.x)  + exp_fast(a.y))  + (exp_fast(a.z)  + exp_fast(a.w));
    float s1 = (exp_fast(b4.x) + exp_fast(b4.y)) + (exp_fast(b4.z) + exp_fast(b4.w));
    float s2 = (exp_fast(c.x)  + exp_fast(c.y))  + (exp_fast(c.z)  + exp_fast(c.w));
    float s3 = (exp_fast(dd.x) + exp_fast(dd.y)) + (exp_fast(dd.z) + exp_fast(dd.w));
    float s  = (s0 + s1) + (s2 + s3);
#pragma unroll
    for (int o2 = 16; o2; o2 >>= 1) s += __shfl_xor_sync(0xffffffffu, s, o2);

    float blank_logit = __shfl_sync(0xffffffffu, dd.w, 31);  // element 511

    if (lane == 0) {
        float lse2;
        asm("lg2.approx.f32 %0, %1;" : "=f"(lse2) : "f"(s));
        int tgt = targets[b * Uu + min(u, Uu - 1)];
        float lab_logit = __ldg(logits + (size_t)gw * Vv + tgt);
        g_blank[o] = fmaf(blank_logit, L2E, -lse2);
        g_lab[o]   = fmaf(lab_logit,   L2E, -lse2);
    }
}

// ---------------------------------------------------------------------------
// Kernel 2: MITM DP, one 64-thread block per batch. Each warp preloads ONLY
// its own half of the tables (two commit groups, ordered by first use), then
// forward(warp0)/backward(warp1) wavefronts meet at cut dm; combine by LSE.
// ---------------------------------------------------------------------------
__global__ void __launch_bounds__(64) dp_kernel(const int* __restrict__ tl_arr,
                                                const int* __restrict__ ul_arr,
                                                float* __restrict__ out) {
    extern __shared__ float sm[];
    float* s_bl  = sm;
    float* s_la  = sm + NDIAG * DSTR;
    float* s_cmb = sm + 2 * NDIAG * DSTR;  // 88 floats: beta on the cut
    int b = blockIdx.x;

    int tl = __ldg(tl_arr + b), ul = __ldg(ul_arr + b);
    int dtar = tl - 1 + ul;
    int dm   = dtar >> 1;

    const float4* gb = reinterpret_cast<const float4*>(g_blank + b * NDIAG * DSTR);
    const float4* gl = reinterpret_cast<const float4*>(g_lab   + b * NDIAG * DSTR);
    unsigned int sb = (unsigned int)__cvta_generic_to_shared(s_bl);
    unsigned int sl = (unsigned int)__cvta_generic_to_shared(s_la);

    int wid  = threadIdx.x >> 5;
    int lane = threadIdx.x & 31;
    int u0   = lane * 4;
    int uoff = min(u0, 84);

    // Per-warp preload of this warp's rows, in two groups ordered by first use.
    // Row range [lo,hi] inclusive -> float4 indices [lo*22, (hi+1)*22).
    int midf = (dm + 1) >> 1;                       // forward: A=[0,midf], B=(midf,dm]
    int midb = (dm + dtar) >> 1;                    // backward: A=[midb-1,dtar], B=[dm,midb-2]
    int a_lo, a_hi, b_lo, b_hi;
    if (wid == 0) { a_lo = 0;                a_hi = midf;  b_lo = midf + 1;  b_hi = dm;       }
    else          { a_lo = max(midb - 1, dm); a_hi = dtar; b_lo = dm;        b_hi = midb - 2; }
    for (int i = a_lo * (DSTR/4) + lane; i < (a_hi + 1) * (DSTR/4); i += 32) {
        cp16(sb + 16u * i, gb + i);
        cp16(sl + 16u * i, gl + i);
    }
    asm volatile("cp.async.commit_group;");
    for (int i = b_lo * (DSTR/4) + lane; i < (b_hi + 1) * (DSTR/4); i += 32) {
        cp16(sb + 16u * i, gb + i);
        cp16(sl + 16u * i, gl + i);
    }
    asm volatile("cp.async.commit_group;");
    asm volatile("cp.async.wait_group 1;");         // group A resident
    __syncwarp();

    if (wid == 1) {
        // ---------------- BACKWARD beta: diag dtar-1 down to dm -------------
        float w0 = NEG_INF, w1 = NEG_INF, w2 = NEG_INF, w3 = NEG_INF;
        float corner = s_bl[dtar * DSTR + ul];     // beta[tl-1][ul] = blank there
        if (lane == (ul >> 2)) {
            int sel = ul & 3;
            if      (sel == 0) w0 = corner;
            else if (sel == 1) w1 = corner;
            else if (sel == 2) w2 = corner;
            else               w3 = corner;
        }
        float wr = __shfl_down_sync(0xffffffffu, w0, 1);   // beta_next[u0+4]

        float4 cbl, cla;
        if (dtar > dm) {
            cbl = *reinterpret_cast<const float4*>(s_bl + (dtar - 1) * DSTR + uoff);
            cla = *reinterpret_cast<const float4*>(s_la + (dtar - 1) * DSTR + uoff);
        }
        int dstop = max(midb, dm);                  // segment 1 floor (rows in A)
#pragma unroll 2
        for (int d = dtar - 1; d >= dstop; --d) {
            int dn = max(d - 1, 0);
            float4 nbl = *reinterpret_cast<const float4*>(s_bl + dn * DSTR + uoff);
            float4 nla = *reinterpret_cast<const float4*>(s_la + dn * DSTR + uoff);
            float nb0 = dstep(w0, w1, cbl.x, cla.x);
            float nwr = __shfl_down_sync(0xffffffffu, nb0, 1);
            float nb1 = dstep(w1, w2, cbl.y, cla.y);
            float nb2 = dstep(w2, w3, cbl.z, cla.z);
            float nb3 = dstep(w3, wr, cbl.w, cla.w);
            w0 = nb0; w1 = nb1; w2 = nb2; w3 = nb3; wr = nwr;
            cbl = nbl; cla = nla;
        }
        asm volatile("cp.async.wait_group 0;");     // group B resident
        __syncwarp();
#pragma unroll 2
        for (int d = dstop - 1; d >= dm; --d) {
            int dn = max(d - 1, 0);
            float4 nbl = *reinterpret_cast<const float4*>(s_bl + dn * DSTR + uoff);
            float4 nla = *reinterpret_cast<const float4*>(s_la + dn * DSTR + uoff);
            float nb0 = dstep(w0, w1, cbl.x, cla.x);
            float nwr = __shfl_down_sync(0xffffffffu, nb0, 1);
            float nb1 = dstep(w1, w2, cbl.y, cla.y);
            float nb2 = dstep(w2, w3, cbl.z, cla.z);
            float nb3 = dstep(w3, wr, cbl.w, cla.w);
            w0 = nb0; w1 = nb1; w2 = nb2; w3 = nb3; wr = nwr;
            cbl = nbl; cla = nla;
        }
        *reinterpret_cast<float4*>(s_cmb + uoff) = make_float4(w0, w1, w2, w3);
        asm volatile("bar.sync 1, 64;" ::: "memory");
        return;
    }

    // ---------------- FORWARD alpha: diag 1 up to dm -------------------------
    float v0 = NEG_INF, v1 = NEG_INF, v2 = NEG_INF, v3 = NEG_INF;
    if (lane == 0) v0 = 0.0f;                      // alpha[0][0] (log2 domain)

    float4 cbl = *reinterpret_cast<const float4*>(s_bl + uoff);   // source row 0
    float4 cla = *reinterpret_cast<const float4*>(s_la + uoff);
    float vleft = NEG_INF;
    float lleft = __shfl_up_sync(0xffffffffu, cla.w, 1);

    int dmid = min(midf, dm);                      // segment 1 ceiling (rows in A)
#pragma unroll 2
    for (int d = 1; d <= dmid; ++d) {
        float4 nbl = *reinterpret_cast<const float4*>(s_bl + d * DSTR + uoff);
        float4 nla = *reinterpret_cast<const float4*>(s_la + d * DSTR + uoff);
        float nv3 = dstep(v3, v2, cbl.w, cla.z);
        float nvl = __shfl_up_sync(0xffffffffu, nv3, 1);
        float nv0 = dstep(v0, vleft, cbl.x, lleft);
        float nv1 = dstep(v1, v0,    cbl.y, cla.x);
        float nv2 = dstep(v2, v1,    cbl.z, cla.y);
        float nll = __shfl_up_sync(0xffffffffu, nla.w, 1);
        vleft = (lane == 0) ? NEG_INF : nvl;
        lleft = nll;
        v0 = nv0; v1 = nv1; v2 = nv2; v3 = nv3;
        cbl = nbl; cla = nla;
    }
    asm volatile("cp.async.wait_group 0;");        // group B resident
    __syncwarp();
#pragma unroll 2
    for (int d = dmid + 1; d <= dm; ++d) {
        float4 nbl = *reinterpret_cast<const float4*>(s_bl + d * DSTR + uoff);
        float4 nla = *reinterpret_cast<const float4*>(s_la + d * DSTR + uoff);
        float nv3 = dstep(v3, v2, cbl.w, cla.z);
        float nvl = __shfl_up_sync(0xffffffffu, nv3, 1);
        float nv0 = dstep(v0, vleft, cbl.x, lleft);
        float nv1 = dstep(v1, v0,    cbl.y, cla.x);
        float nv2 = dstep(v2, v1,    cbl.z, cla.y);
        float nll = __shfl_up_sync(0xffffffffu, nla.w, 1);
        vleft = (lane == 0) ? NEG_INF : nvl;
        lleft = nll;
        v0 = nv0; v1 = nv1; v2 = nv2; v3 = nv3;
        cbl = nbl; cla = nla;
    }

    asm volatile("bar.sync 1, 64;" ::: "memory");

    // ---------------- Combine at the cut: LSE over valid u -------------------
    float4 bt = *reinterpret_cast<const float4*>(s_cmb + uoff);
    int lo = max(0, dm - (tl - 1));
    int hi = min(dm, ul);
    float t0 = (u0     >= lo && u0     <= hi) ? v0 + bt.x : NEG_INF;
    float t1 = (u0 + 1 >= lo && u0 + 1 <= hi) ? v1 + bt.y : NEG_INF;
    float t2 = (u0 + 2 >= lo && u0 + 2 <= hi) ? v2 + bt.z : NEG_INF;
    float t3 = (u0 + 3 >= lo && u0 + 3 <= hi) ? v3 + bt.w : NEG_INF;

    float m = fmaxf(fmaxf(t0, t1), fmaxf(t2, t3));
#pragma unroll
    for (int o = 16; o; o >>= 1) m = fmaxf(m, __shfl_xor_sync(0xffffffffu, m, o));

    float e0, e1, e2, e3;
    asm("ex2.approx.f32 %0, %1;" : "=f"(e0) : "f"(t0 - m));
    asm("ex2.approx.f32 %0, %1;" : "=f"(e1) : "f"(t1 - m));
    asm("ex2.approx.f32 %0, %1;" : "=f"(e2) : "f"(t2 - m));
    asm("ex2.approx.f32 %0, %1;" : "=f"(e3) : "f"(t3 - m));
    float s = (e0 + e1) + (e2 + e3);
#pragma unroll
    for (int o = 16; o; o >>= 1) s += __shfl_xor_sync(0xffffffffu, s, o);

    if (lane == 0) {
        float l;  asm("lg2.approx.f32 %0, %1;" : "=f"(l) : "f"(s));
        g_ll[b] = m + l;                          // log2-domain log-likelihood
        __threadfence();
        int prev = atomicAdd(&g_done, 1);
        if (prev == Bb - 1) {                     // deterministic final reduce
            __threadfence();
            float sll = 0.0f;
#pragma unroll
            for (int i = 0; i < Bb; ++i) sll += __ldcg(&g_ll[i]);
            out[0] = sll * (-LN2 / (float)Bb);
            g_done = 0;                           // reset for next graph replay
        }
    }
}

extern "C" void kernel_launch(void* const* d_in, const int* in_sizes, int n_in,
                              void* d_out, int out_size) {
    const float* logits  = (const float*)d_in[0];
    const int*   targets = (const int*)d_in[1];
    const int*   tl      = (const int*)d_in[2];
    const int*   ul      = (const int*)d_in[3];

    const int ROWS = Bb * Tt * U1;                 // 207360 rows, 8 warps/block
    lse_kernel<<<PADB + ROWS / 8, 256>>>(logits, targets, tl, ul);

    size_t smem = (2 * NDIAG * DSTR + 128) * sizeof(float);  // tables + cut buf
    cudaFuncSetAttribute(dp_kernel, cudaFuncAttributeMaxDynamicSharedMemorySize, (int)smem);
    dp_kernel<<<Bb, 64, smem>>>(tl, ul, (float*)d_out);
}